// round 9
// baseline (speedup 1.0000x reference)
#include <cuda_runtime.h>

// 2-level 3D inverse db4 DWT.
// Kernel A: fused x+y synthesis per z-slice (smem, float2-vectorized stage y).
// Kernel B: streaming z synthesis, float4 per thread, z-segmented.
// out[i] = sum_d lo[(i>>1)+d]*CLO[i&1][d] + hi[(i>>1)+d]*CHI[i&1][d]

#define BC 16  // batch * channels

// db4: CLO[p][d] = g0[6+p-2d], CHI[p][d] = g1[6+p-2d]; literals -> FFMA-imm
#define CLO00  0.032883011666982945f
#define CLO01 -0.18703481171888114f
#define CLO02  0.6308807679295904f
#define CLO03  0.23037781330885523f
#define CLO10 -0.010597401784997278f
#define CLO11  0.030841381835986965f
#define CLO12 -0.02798376941698385f
#define CLO13  0.7148465705525415f
#define CHI00  0.7148465705525415f
#define CHI01 -0.02798376941698385f
#define CHI02  0.030841381835986965f
#define CHI03 -0.010597401784997278f
#define CHI10 -0.23037781330885523f
#define CHI11 -0.6308807679295904f
#define CHI12  0.18703481171888114f
#define CHI13 -0.032883011666982945f

#define SYNTH(l0,l1,l2,l3,h0,h1,h2,h3,o0,o1)                              \
    do {                                                                  \
        o0 = l0*CLO00 + l1*CLO01 + l2*CLO02 + l3*CLO03                    \
           + h0*CHI00 + h1*CHI01 + h2*CHI02 + h3*CHI03;                   \
        o1 = l0*CLO10 + l1*CLO11 + l2*CLO12 + l3*CLO13                    \
           + h0*CHI10 + h1*CHI11 + h2*CHI12 + h3*CHI13;                   \
    } while (0)

// Scratch: xy-fused output [2][BC][Nz][M][M] (sized for level 0), + level-1 LL
__device__ float g_U[2ull * BC * 66 * 126 * 126];
__device__ float g_LL[(size_t)BC * 66 * 66 * 66];

// ---------------- Kernel A: fused x+y synthesis for one z-slice ----------------
// grid = (Nz, 2 trees, BC), 512 threads. smem t: [2][N][MP], MP = M+2 (even ->
// float2-aligned rows; warp accesses are row-contiguous so no bank conflicts).
template<int N, bool LOW_LL>
__global__ __launch_bounds__(512)
void k_xy(const float* __restrict__ low_in, const float* __restrict__ highs) {
    constexpr int M  = 2 * N - 6;
    constexpr int MP = M + 2;      // even -> aligned float2 smem rows
    constexpr int P  = N - 3;      // output pairs per axis
    extern __shared__ float t[];   // 2*N*MP floats

    const float* low = LOW_LL ? g_LL : low_in;
    const int z = blockIdx.x, i = blockIdx.y, b = blockIdx.z;
    const int tid = threadIdx.x;
    const size_t V  = (size_t)N * N * N;
    const size_t zb = (size_t)z * N * N;

    // ---- stage x: pair-threads along rows; both sub-trees in one loop ----
    {
        const int px = tid & 63;
        const int y0 = tid >> 6;        // 0..7
        const int gl0 = 4 * i;
        const float* lo0 = (gl0 == 0) ? (low + (size_t)b * V)
                                      : (highs + ((size_t)b * 7 + (gl0 - 1)) * V);
        const float* hi0 = highs + ((size_t)b * 7 + gl0) * V;
        const float* lo1 = highs + ((size_t)b * 7 + (4 * i + 1)) * V;
        const float* hi1 = highs + ((size_t)b * 7 + (4 * i + 2)) * V;
        if (px < P) {
            for (int y = y0; y < N; y += 8) {
                const size_t ro = zb + (size_t)y * N + px;
                const float* a = lo0 + ro;  const float* c = hi0 + ro;
                const float* e = lo1 + ro;  const float* f = hi1 + ro;
                float a0 = a[0], a1 = a[1], a2 = a[2], a3 = a[3];
                float c0 = c[0], c1 = c[1], c2 = c[2], c3 = c[3];
                float e0 = e[0], e1 = e[1], e2 = e[2], e3 = e[3];
                float f0 = f[0], f1 = f[1], f2 = f[2], f3 = f[3];
                float o0, o1, p0, p1;
                SYNTH(a0, a1, a2, a3, c0, c1, c2, c3, o0, o1);
                SYNTH(e0, e1, e2, e3, f0, f1, f2, f3, p0, p1);
                *(float2*)&t[y * MP + 2 * px]       = make_float2(o0, o1);
                *(float2*)&t[(N + y) * MP + 2 * px] = make_float2(p0, p1);
            }
        }
    }
    __syncthreads();

    // ---- stage y: float2 per thread along x; write g_U[i][b][z][*][*] ----
    {
        const int x2  = tid & 63;       // float2 index
        const int x   = 2 * x2;
        const int py0 = tid >> 6;       // 0..7
        if (x < M) {
            float* ub = g_U + ((((size_t)i * BC + b) * N + z) * M) * M + x;
            for (int py = py0; py < P; py += 8) {
                const float* r0 = &t[py * MP + x];        // sub-tree lo rows
                const float* r1 = &t[(N + py) * MP + x];  // sub-tree hi rows
                float2 l0 = *(const float2*)&r0[0];
                float2 l1 = *(const float2*)&r0[MP];
                float2 l2 = *(const float2*)&r0[2 * MP];
                float2 l3 = *(const float2*)&r0[3 * MP];
                float2 h0 = *(const float2*)&r1[0];
                float2 h1 = *(const float2*)&r1[MP];
                float2 h2 = *(const float2*)&r1[2 * MP];
                float2 h3 = *(const float2*)&r1[3 * MP];
                float2 o0, o1;
                SYNTH(l0.x, l1.x, l2.x, l3.x, h0.x, h1.x, h2.x, h3.x, o0.x, o1.x);
                SYNTH(l0.y, l1.y, l2.y, l3.y, h0.y, h1.y, h2.y, h3.y, o0.y, o1.y);
                float* d = ub + (size_t)(2 * py) * M;
                *(float2*)&d[0] = o0;
                *(float2*)&d[M] = o1;
            }
        }
    }
}

// ---------------- Kernel B: streaming z synthesis, float4, z-segmented ----------------
// g_U[0][b] = lo tree, g_U[1][b] = hi tree, each [NZ][plane]. grid.y = segment,
// grid.z = b. Each segment handles output pairs [p0, p1) (3-slice read overlap).
template<int NZ, int SEG, bool TO_LL>
__global__ __launch_bounds__(256)
void k_z(float* __restrict__ out_in, int plane4) {   // plane4 = plane/4
    const int pix = blockIdx.x * 256 + threadIdx.x;
    if (pix >= plane4) return;
    const int seg = blockIdx.y;
    const int b   = blockIdx.z;
    constexpr int MZ = 2 * NZ - 6;
    constexpr int P  = NZ - 3;
    constexpr int CH = (P + SEG - 1) / SEG;

    const int p0 = seg * CH;
    const int p1 = (p0 + CH < P) ? (p0 + CH) : P;

    float* out = TO_LL ? g_LL : out_in;
    const float4* lo = (const float4*)g_U + (size_t)b * NZ * plane4 + pix;
    const float4* hi = (const float4*)g_U + ((size_t)BC + b) * (size_t)NZ * plane4 + pix;
    float4* ob = (float4*)out + (size_t)b * MZ * plane4 + pix;

    float4 l0 = lo[(size_t)p0 * plane4];
    float4 l1 = lo[(size_t)(p0 + 1) * plane4];
    float4 l2 = lo[(size_t)(p0 + 2) * plane4];
    float4 h0 = hi[(size_t)p0 * plane4];
    float4 h1 = hi[(size_t)(p0 + 1) * plane4];
    float4 h2 = hi[(size_t)(p0 + 2) * plane4];
#pragma unroll 2
    for (int bz = p0; bz < p1; ++bz) {
        float4 l3 = lo[(size_t)(bz + 3) * plane4];
        float4 h3 = hi[(size_t)(bz + 3) * plane4];
        float4 o0, o1;
        SYNTH(l0.x, l1.x, l2.x, l3.x, h0.x, h1.x, h2.x, h3.x, o0.x, o1.x);
        SYNTH(l0.y, l1.y, l2.y, l3.y, h0.y, h1.y, h2.y, h3.y, o0.y, o1.y);
        SYNTH(l0.z, l1.z, l2.z, l3.z, h0.z, h1.z, h2.z, h3.z, o0.z, o1.z);
        SYNTH(l0.w, l1.w, l2.w, l3.w, h0.w, h1.w, h2.w, h3.w, o0.w, o1.w);
        ob[(size_t)(2 * bz) * plane4]     = o0;
        ob[(size_t)(2 * bz + 1) * plane4] = o1;
        l0 = l1; l1 = l2; l2 = l3;
        h0 = h1; h1 = h2; h2 = h3;
    }
}

extern "C" void kernel_launch(void* const* d_in, const int* in_sizes, int n_in,
                              void* d_out, int out_size) {
    const float *yl = nullptr, *yh0 = nullptr, *yh1 = nullptr;
    for (int i = 0; i < n_in; ++i) {
        if      (in_sizes[i] == 746496)   yl  = (const float*)d_in[i];  // (2,8,36,36,36)
        else if (in_sizes[i] == 32199552) yh0 = (const float*)d_in[i];  // (2,8,7,66,66,66)
        else if (in_sizes[i] == 5225472)  yh1 = (const float*)d_in[i];  // (2,8,7,36,36,36)
    }
    float* out = (float*)d_out;

    constexpr int SMEM1 = 2 * 36 * 68 * 4;   // 19,584 B
    constexpr int SMEM0 = 2 * 66 * 128 * 4;  // 67,584 B
    static bool attr_done = false;
    if (!attr_done) {
        cudaFuncSetAttribute(k_xy<66, true>,
                             cudaFuncAttributeMaxDynamicSharedMemorySize, SMEM0);
        attr_done = true;
    }

    // ---- Level 1: 36 -> 66 ----
    k_xy<36, false><<<dim3(36, 2, BC), 512, SMEM1>>>(yl, yh1);
    {
        int plane4 = 66 * 66 / 4;                  // 1089
        k_z<36, 2, true><<<dim3((plane4 + 255) / 256, 2, BC), 256>>>(nullptr, plane4);
    }

    // ---- Level 0: 66 -> 126 ----
    k_xy<66, true><<<dim3(66, 2, BC), 512, SMEM0>>>(nullptr, yh0);
    {
        int plane4 = 126 * 126 / 4;                // 3969
        k_z<66, 4, false><<<dim3((plane4 + 255) / 256, 4, BC), 256>>>(out, plane4);
    }
}